// round 1
// baseline (speedup 1.0000x reference)
#include <cuda_runtime.h>
#include <math.h>

// Problem constants (fixed by the reference)
#define SEQ   2048
#define HD    64
#define BM    64
#define BN    64
#define PAD   4
#define LDS   (HD + PAD)          // 68 floats per smem row (16B-aligned stride)
#define LOG2E 1.4426950408889634f

// Dynamic smem layout: sQT[D][BM] | sKT[D][BN] | sV[BN][D] | sPT[BN][BM]
#define SMEM_FLOATS (4 * 64 * LDS)
#define SMEM_BYTES  (SMEM_FLOATS * 4)

__global__ __launch_bounds__(256, 1)
void flash_fp32_kernel(const float* __restrict__ Q,
                       const float* __restrict__ K,
                       const float* __restrict__ V,
                       const float* __restrict__ M,
                       float* __restrict__ O)
{
    extern __shared__ float sm[];
    float* sQT = sm;                    // [HD][BM]  (transposed)
    float* sKT = sQT + HD * LDS;        // [HD][BN]  (transposed)
    float* sV  = sKT + HD * LDS;        // [BN][HD]  (row-major)
    float* sPT = sV  + BN * LDS;        // [BN][BM]  (P transposed: sPT[k][i])

    const int tid = threadIdx.x;
    const int tx  = tid & 15;           // 16 threads across columns
    const int ty  = tid >> 4;           // 16 threads across rows
    const int bh  = blockIdx.y;         // fused (b, h)
    const int qt  = blockIdx.x;         // Q tile index

    const float* Qb = Q + ((size_t)bh * SEQ + (size_t)qt * BM) * HD;
    const float* Kb = K + (size_t)bh * SEQ * HD;
    const float* Vb = V + (size_t)bh * SEQ * HD;

    // ---- Load Q tile (transposed into sQT[d][row]) ----
    #pragma unroll
    for (int s = tid; s < BM * 16; s += 256) {
        int row = s >> 4;
        int d0  = (s & 15) * 4;
        float4 v = *(const float4*)(Qb + row * HD + d0);
        sQT[(d0 + 0) * LDS + row] = v.x;
        sQT[(d0 + 1) * LDS + row] = v.y;
        sQT[(d0 + 2) * LDS + row] = v.z;
        sQT[(d0 + 3) * LDS + row] = v.w;
    }

    float m_r[4], l_r[4], acc[4][4];
    #pragma unroll
    for (int r = 0; r < 4; r++) {
        m_r[r] = -INFINITY;
        l_r[r] = 0.0f;
        #pragma unroll
        for (int c = 0; c < 4; c++) acc[r][c] = 0.0f;
    }

    const int q0 = qt * BM + ty * 4;    // global Q row of this thread's first row

    for (int kt = 0; kt < SEQ / BN; kt++) {
        __syncthreads();   // previous iter finished reading sKT/sV/sPT

        // ---- Load K tile (transposed) + V tile (row-major) ----
        const float* Kt = Kb + (size_t)kt * BN * HD;
        const float* Vt = Vb + (size_t)kt * BN * HD;
        #pragma unroll
        for (int s = tid; s < BN * 16; s += 256) {
            int row = s >> 4;
            int d0  = (s & 15) * 4;
            float4 v = *(const float4*)(Kt + row * HD + d0);
            sKT[(d0 + 0) * LDS + row] = v.x;
            sKT[(d0 + 1) * LDS + row] = v.y;
            sKT[(d0 + 2) * LDS + row] = v.z;
            sKT[(d0 + 3) * LDS + row] = v.w;
            float4 w = *(const float4*)(Vt + row * HD + d0);
            *(float4*)(sV + row * LDS + d0) = w;
        }
        __syncthreads();

        // ---- GEMM1: sv = Q K^T (+ mask, scale = 1) ----
        float sv[4][4];
        {
            const float* Mb = M + (size_t)q0 * SEQ + (size_t)kt * BN + tx * 4;
            #pragma unroll
            for (int r = 0; r < 4; r++) {
                float4 mv = *(const float4*)(Mb + (size_t)r * SEQ);
                sv[r][0] = mv.x; sv[r][1] = mv.y; sv[r][2] = mv.z; sv[r][3] = mv.w;
            }
        }
        #pragma unroll 8
        for (int d = 0; d < HD; d++) {
            float4 a = *(const float4*)(sQT + d * LDS + ty * 4);
            float4 b = *(const float4*)(sKT + d * LDS + tx * 4);
            float av[4] = {a.x, a.y, a.z, a.w};
            float bv[4] = {b.x, b.y, b.z, b.w};
            #pragma unroll
            for (int r = 0; r < 4; r++)
                #pragma unroll
                for (int c = 0; c < 4; c++)
                    sv[r][c] = fmaf(av[r], bv[c], sv[r][c]);
        }

        // ---- Online softmax update ----
        #pragma unroll
        for (int r = 0; r < 4; r++) {
            float mloc = fmaxf(fmaxf(sv[r][0], sv[r][1]), fmaxf(sv[r][2], sv[r][3]));
            #pragma unroll
            for (int o = 8; o >= 1; o >>= 1)
                mloc = fmaxf(mloc, __shfl_xor_sync(0xffffffffu, mloc, o, 16));

            float mnew = fmaxf(m_r[r], mloc);
            float corr = exp2f((m_r[r] - mnew) * LOG2E);
            m_r[r] = mnew;

            float rowsum = 0.0f;
            #pragma unroll
            for (int c = 0; c < 4; c++) {
                float p = exp2f((sv[r][c] - mnew) * LOG2E);
                sv[r][c] = p;
                rowsum += p;
            }
            #pragma unroll
            for (int o = 8; o >= 1; o >>= 1)
                rowsum += __shfl_xor_sync(0xffffffffu, rowsum, o, 16);

            l_r[r] = l_r[r] * corr + rowsum;
            #pragma unroll
            for (int c = 0; c < 4; c++) acc[r][c] *= corr;

            // store P transposed: sPT[k_local][row_local]
            #pragma unroll
            for (int c = 0; c < 4; c++)
                sPT[(tx * 4 + c) * LDS + ty * 4 + r] = sv[r][c];
        }
        __syncthreads();

        // ---- GEMM2: acc += P V ----
        #pragma unroll 8
        for (int k = 0; k < BN; k++) {
            float4 a = *(const float4*)(sPT + k * LDS + ty * 4);
            float4 b = *(const float4*)(sV  + k * LDS + tx * 4);
            float av[4] = {a.x, a.y, a.z, a.w};
            float bv[4] = {b.x, b.y, b.z, b.w};
            #pragma unroll
            for (int r = 0; r < 4; r++)
                #pragma unroll
                for (int c = 0; c < 4; c++)
                    acc[r][c] = fmaf(av[r], bv[c], acc[r][c]);
        }
    }

    // ---- Epilogue: normalize and store ----
    float* Ob = O + ((size_t)bh * SEQ + (size_t)qt * BM) * HD;
    #pragma unroll
    for (int r = 0; r < 4; r++) {
        float inv = 1.0f / l_r[r];
        float4 o;
        o.x = acc[r][0] * inv;
        o.y = acc[r][1] * inv;
        o.z = acc[r][2] * inv;
        o.w = acc[r][3] * inv;
        *(float4*)(Ob + (size_t)(ty * 4 + r) * HD + tx * 4) = o;
    }
}

extern "C" void kernel_launch(void* const* d_in, const int* in_sizes, int n_in,
                              void* d_out, int out_size)
{
    const float* Q = (const float*)d_in[0];
    const float* K = (const float*)d_in[1];
    const float* V = (const float*)d_in[2];
    const float* M = (const float*)d_in[3];
    float* O = (float*)d_out;

    int bh = in_sizes[0] / (SEQ * HD);   // B*H = 64

    cudaFuncSetAttribute(flash_fp32_kernel,
                         cudaFuncAttributeMaxDynamicSharedMemorySize, SMEM_BYTES);

    dim3 grid(SEQ / BM, bh);
    flash_fp32_kernel<<<grid, 256, SMEM_BYTES>>>(Q, K, V, M, O);
}

// round 6
// speedup vs baseline: 3.5157x; 3.5157x over previous
#include <cuda_runtime.h>
#include <cuda_bf16.h>
#include <cstdint>
#include <math.h>

#define SEQ   2048
#define HD    64
#define BM    128
#define BN    64
#define LOG2E 1.4426950408889634f

// smem byte offsets: bf16 tiles, 128-byte rows (64 bf16), SW128 swizzle
#define SQHI 0
#define SQLO (16*1024)
#define SKHI (32*1024)
#define SKLO (40*1024)
#define SVHI (48*1024)
#define SVLO (56*1024)
#define SMEM_TOTAL (64*1024)

__device__ __forceinline__ uint32_t sw(uint32_t o) { return o ^ ((o >> 3) & 0x70); }

__device__ __forceinline__ uint32_t smem_u32(const void* p) {
    uint32_t a;
    asm("{ .reg .u64 t; cvta.to.shared.u64 t, %1; cvt.u32.u64 %0, t; }" : "=r"(a) : "l"(p));
    return a;
}

__device__ __forceinline__ void ldsm4(uint32_t r[4], uint32_t a) {
    asm volatile("ldmatrix.sync.aligned.m8n8.x4.shared.b16 {%0,%1,%2,%3}, [%4];"
                 : "=r"(r[0]), "=r"(r[1]), "=r"(r[2]), "=r"(r[3]) : "r"(a));
}
__device__ __forceinline__ void ldsm4t(uint32_t r[4], uint32_t a) {
    asm volatile("ldmatrix.sync.aligned.m8n8.x4.trans.shared.b16 {%0,%1,%2,%3}, [%4];"
                 : "=r"(r[0]), "=r"(r[1]), "=r"(r[2]), "=r"(r[3]) : "r"(a));
}

__device__ __forceinline__ void mma_bf16(float d[4], const uint32_t a[4], const uint32_t b[2]) {
    asm volatile("mma.sync.aligned.m16n8k16.row.col.f32.bf16.bf16.f32 "
                 "{%0,%1,%2,%3}, {%4,%5,%6,%7}, {%8,%9}, {%0,%1,%2,%3};"
                 : "+f"(d[0]), "+f"(d[1]), "+f"(d[2]), "+f"(d[3])
                 : "r"(a[0]), "r"(a[1]), "r"(a[2]), "r"(a[3]), "r"(b[0]), "r"(b[1]));
}

// pack two fp32 -> bf16x2 (x in low half = even col, y in high half)
__device__ __forceinline__ uint32_t pk(float x, float y) {
    uint32_t r;
    asm("cvt.rn.bf16x2.f32 %0, %1, %2;" : "=r"(r) : "f"(y), "f"(x));
    return r;
}
__device__ __forceinline__ void hilo(float x, float& h, float& l) {
    h = __bfloat162float(__float2bfloat16(x));
    l = x - h;
}
__device__ __forceinline__ float ex2(float x) {
    float y;
    asm("ex2.approx.ftz.f32 %0, %1;" : "=f"(y) : "f"(x));
    return y;
}

__global__ __launch_bounds__(128, 2)
void flash_mma_kernel(const float* __restrict__ Q,
                      const float* __restrict__ K,
                      const float* __restrict__ V,
                      const float* __restrict__ Mk,
                      float* __restrict__ O)
{
    extern __shared__ char smem[];
    const uint32_t sb = smem_u32(smem);
    const int tid  = threadIdx.x;
    const int lane = tid & 31;
    const int wid  = tid >> 5;
    const int bh   = blockIdx.y;
    const int qt   = blockIdx.x;

    const float* Qb = Q + ((size_t)bh * SEQ + (size_t)qt * BM) * HD;
    const float* Kb = K + (size_t)bh * SEQ * HD;
    const float* Vb = V + (size_t)bh * SEQ * HD;

    // ldmatrix thread-group decomposition
    const int g  = lane >> 3;   // 0..3 (8x8 tile index within x4)
    const int i8 = lane & 7;    // row within tile

    // ---- Load Q tile once (hi/lo bf16, swizzled) ----
    for (int j = tid; j < BM * 16; j += 128) {
        int row = j >> 4, c = j & 15;
        float4 v = *(const float4*)(Qb + row * HD + c * 4);
        float hx, lx, hy, ly, hz, lz, hw, lw;
        hilo(v.x, hx, lx); hilo(v.y, hy, ly); hilo(v.z, hz, lz); hilo(v.w, hw, lw);
        uint32_t o = sw(row * 128 + c * 8);
        *(uint2*)(smem + SQHI + o) = make_uint2(pk(hx, hy), pk(hz, hw));
        *(uint2*)(smem + SQLO + o) = make_uint2(pk(lx, ly), pk(lz, lw));
    }

    float Sacc[2][8][4];           // S / P tiles (fp32), reused per iter
    float Oacc[2][8][4];           // un-normalized output accumulator
    float lsum[2][2];              // row sums: [mt][row-half]
    #pragma unroll
    for (int mt = 0; mt < 2; mt++) {
        lsum[mt][0] = 0.0f; lsum[mt][1] = 0.0f;
        #pragma unroll
        for (int nt = 0; nt < 8; nt++)
            #pragma unroll
            for (int e = 0; e < 4; e++) Oacc[mt][nt][e] = 0.0f;
    }

    for (int kt = 0; kt < SEQ / BN; kt++) {
        __syncthreads();   // previous iter's fragments consumed

        // ---- Load K, V tiles (hi/lo bf16, swizzled) ----
        const float* Kt = Kb + (size_t)kt * BN * HD;
        const float* Vt = Vb + (size_t)kt * BN * HD;
        #pragma unroll
        for (int j = tid; j < BN * 16; j += 128) {
            int row = j >> 4, c = j & 15;
            uint32_t o = sw(row * 128 + c * 8);
            float4 v = *(const float4*)(Kt + row * HD + c * 4);
            float hx, lx, hy, ly, hz, lz, hw, lw;
            hilo(v.x, hx, lx); hilo(v.y, hy, ly); hilo(v.z, hz, lz); hilo(v.w, hw, lw);
            *(uint2*)(smem + SKHI + o) = make_uint2(pk(hx, hy), pk(hz, hw));
            *(uint2*)(smem + SKLO + o) = make_uint2(pk(lx, ly), pk(lz, lw));
            float4 w = *(const float4*)(Vt + row * HD + c * 4);
            hilo(w.x, hx, lx); hilo(w.y, hy, ly); hilo(w.z, hz, lz); hilo(w.w, hw, lw);
            *(uint2*)(smem + SVHI + o) = make_uint2(pk(hx, hy), pk(hz, hw));
            *(uint2*)(smem + SVLO + o) = make_uint2(pk(lx, ly), pk(lz, lw));
        }
        __syncthreads();

        // ---- GEMM1: S = Q K^T  (3-pass hi/lo compensation) ----
        #pragma unroll
        for (int mt = 0; mt < 2; mt++)
            #pragma unroll
            for (int nt = 0; nt < 8; nt++)
                #pragma unroll
                for (int e = 0; e < 4; e++) Sacc[mt][nt][e] = 0.0f;

        #pragma unroll
        for (int kc = 0; kc < 4; kc++) {
            uint32_t aQh[2][4], aQl[2][4];
            #pragma unroll
            for (int mt = 0; mt < 2; mt++) {
                uint32_t arow = wid * 32 + mt * 16 + (g & 1) * 8 + i8;
                uint32_t acol = kc * 16 + (g >> 1) * 8;
                uint32_t o = sw(arow * 128 + acol * 2);
                ldsm4(aQh[mt], sb + SQHI + o);
                ldsm4(aQl[mt], sb + SQLO + o);
            }
            #pragma unroll
            for (int nt2 = 0; nt2 < 4; nt2++) {
                uint32_t brow = nt2 * 16 + (g >> 1) * 8 + i8;
                uint32_t bcol = kc * 16 + (g & 1) * 8;
                uint32_t o = sw(brow * 128 + bcol * 2);
                uint32_t bKh[4], bKl[4];
                ldsm4(bKh, sb + SKHI + o);
                ldsm4(bKl, sb + SKLO + o);
                #pragma unroll
                for (int mt = 0; mt < 2; mt++)
                    #pragma unroll
                    for (int h = 0; h < 2; h++) {
                        mma_bf16(Sacc[mt][nt2 * 2 + h], aQh[mt], bKh + 2 * h);
                        mma_bf16(Sacc[mt][nt2 * 2 + h], aQh[mt], bKl + 2 * h);
                        mma_bf16(Sacc[mt][nt2 * 2 + h], aQl[mt], bKh + 2 * h);
                    }
            }
        }

        // ---- softmax: p = exp(s + mask), accumulate row sums (no max sub) ----
        #pragma unroll
        for (int mt = 0; mt < 2; mt++) {
            int grow = qt * BM + wid * 32 + mt * 16 + (lane >> 2);
            #pragma unroll
            for (int nt = 0; nt < 8; nt++) {
                int gcol = kt * BN + nt * 8 + 2 * (lane & 3);
                float2 m0 = *(const float2*)(Mk + (size_t)grow * SEQ + gcol);
                float2 m1 = *(const float2*)(Mk + (size_t)(grow + 8) * SEQ + gcol);
                float p0 = ex2((Sacc[mt][nt][0] + m0.x) * LOG2E);
                float p1 = ex2((Sacc[mt][nt][1] + m0.y) * LOG2E);
                float p2 = ex2((Sacc[mt][nt][2] + m1.x) * LOG2E);
                float p3 = ex2((Sacc[mt][nt][3] + m1.y) * LOG2E);
                lsum[mt][0] += p0 + p1;
                lsum[mt][1] += p2 + p3;
                Sacc[mt][nt][0] = p0; Sacc[mt][nt][1] = p1;
                Sacc[mt][nt][2] = p2; Sacc[mt][nt][3] = p3;
            }
        }

        // ---- GEMM2: O += P V  (P from registers; 3-pass hi/lo) ----
        #pragma unroll
        for (int kc = 0; kc < 4; kc++) {
            uint32_t aPh[2][4], aPl[2][4];
            #pragma unroll
            for (int mt = 0; mt < 2; mt++) {
                const float* t0 = Sacc[mt][2 * kc];
                const float* t1 = Sacc[mt][2 * kc + 1];
                float h0, l0, h1, l1, h2, l2, h3, l3;
                hilo(t0[0], h0, l0); hilo(t0[1], h1, l1);
                hilo(t0[2], h2, l2); hilo(t0[3], h3, l3);
                aPh[mt][0] = pk(h0, h1); aPl[mt][0] = pk(l0, l1);
                aPh[mt][1] = pk(h2, h3); aPl[mt][1] = pk(l2, l3);
                hilo(t1[0], h0, l0); hilo(t1[1], h1, l1);
                hilo(t1[2], h2, l2); hilo(t1[3], h3, l3);
                aPh[mt][2] = pk(h0, h1); aPl[mt][2] = pk(l0, l1);
                aPh[mt][3] = pk(h2, h3); aPl[mt][3] = pk(l2, l3);
            }
            #pragma unroll
            for (int nt2 = 0; nt2 < 4; nt2++) {
                uint32_t vrow = kc * 16 + (g & 1) * 8 + i8;
                uint32_t vcol = nt2 * 16 + (g >> 1) * 8;
                uint32_t o = sw(vrow * 128 + vcol * 2);
                uint32_t bVh[4], bVl[4];
                ldsm4t(bVh, sb + SVHI + o);
                ldsm4t(bVl, sb + SVLO + o);
                #pragma unroll
                for (int mt = 0; mt < 2; mt++)
                    #pragma unroll
                    for (int h = 0; h < 2; h++) {
                        mma_bf16(Oacc[mt][nt2 * 2 + h], aPh[mt], bVh + 2 * h);
                        mma_bf16(Oacc[mt][nt2 * 2 + h], aPh[mt], bVl + 2 * h);
                        mma_bf16(Oacc[mt][nt2 * 2 + h], aPl[mt], bVh + 2 * h);
                    }
            }
        }
    }

    // ---- epilogue: reduce lsum over the 4 lanes sharing each row, normalize ----
    #pragma unroll
    for (int mt = 0; mt < 2; mt++)
        #pragma unroll
        for (int hh = 0; hh < 2; hh++) {
            float s = lsum[mt][hh];
            s += __shfl_xor_sync(0xffffffffu, s, 1);
            s += __shfl_xor_sync(0xffffffffu, s, 2);
            lsum[mt][hh] = s;
        }

    #pragma unroll
    for (int mt = 0; mt < 2; mt++) {
        float inv0 = 1.0f / lsum[mt][0];
        float inv1 = 1.0f / lsum[mt][1];
        int grow = qt * BM + wid * 32 + mt * 16 + (lane >> 2);
        float* o0 = O + ((size_t)bh * SEQ + grow) * HD;
        float* o1 = O + ((size_t)bh * SEQ + grow + 8) * HD;
        #pragma unroll
        for (int nt = 0; nt < 8; nt++) {
            int c = nt * 8 + 2 * (lane & 3);
            *(float2*)(o0 + c) = make_float2(Oacc[mt][nt][0] * inv0, Oacc[mt][nt][1] * inv0);
            *(float2*)(o1 + c) = make_float2(Oacc[mt][nt][2] * inv1, Oacc[mt][nt][3] * inv1);
        }
    }
}

extern "C" void kernel_launch(void* const* d_in, const int* in_sizes, int n_in,
                              void* d_out, int out_size)
{
    const float* Q  = (const float*)d_in[0];
    const float* K  = (const float*)d_in[1];
    const float* V  = (const float*)d_in[2];
    const float* Mk = (const float*)d_in[3];
    float* O = (float*)d_out;

    int bh = in_sizes[0] / (SEQ * HD);   // B*H = 64

    cudaFuncSetAttribute(flash_mma_kernel,
                         cudaFuncAttributeMaxDynamicSharedMemorySize, SMEM_TOTAL);

    dim3 grid(SEQ / BM, bh);
    flash_mma_kernel<<<grid, 128, SMEM_TOTAL>>>(Q, K, V, Mk, O);
}

// round 7
// speedup vs baseline: 3.6937x; 1.0506x over previous
#include <cuda_runtime.h>
#include <cuda_bf16.h>
#include <cstdint>
#include <math.h>

#define SEQ   2048
#define HD    64
#define BM    128
#define BN    64
#define LOG2E 1.4426950408889634f

// smem byte offsets: 128-byte rows (64 x 16-bit), SW128 swizzle
#define SQHI 0
#define SQLO (16*1024)
#define SKHI (32*1024)
#define SKLO (40*1024)
#define SV   (48*1024)
#define SMEM_TOTAL (56*1024)

__device__ __forceinline__ uint32_t sw(uint32_t o) { return o ^ ((o >> 3) & 0x70); }

__device__ __forceinline__ uint32_t smem_u32(const void* p) {
    uint32_t a;
    asm("{ .reg .u64 t; cvta.to.shared.u64 t, %1; cvt.u32.u64 %0, t; }" : "=r"(a) : "l"(p));
    return a;
}

__device__ __forceinline__ void ldsm4(uint32_t r[4], uint32_t a) {
    asm volatile("ldmatrix.sync.aligned.m8n8.x4.shared.b16 {%0,%1,%2,%3}, [%4];"
                 : "=r"(r[0]), "=r"(r[1]), "=r"(r[2]), "=r"(r[3]) : "r"(a));
}
__device__ __forceinline__ void ldsm4t(uint32_t r[4], uint32_t a) {
    asm volatile("ldmatrix.sync.aligned.m8n8.x4.trans.shared.b16 {%0,%1,%2,%3}, [%4];"
                 : "=r"(r[0]), "=r"(r[1]), "=r"(r[2]), "=r"(r[3]) : "r"(a));
}

__device__ __forceinline__ void mma_bf16(float d[4], const uint32_t a[4], const uint32_t b[2]) {
    asm volatile("mma.sync.aligned.m16n8k16.row.col.f32.bf16.bf16.f32 "
                 "{%0,%1,%2,%3}, {%4,%5,%6,%7}, {%8,%9}, {%0,%1,%2,%3};"
                 : "+f"(d[0]), "+f"(d[1]), "+f"(d[2]), "+f"(d[3])
                 : "r"(a[0]), "r"(a[1]), "r"(a[2]), "r"(a[3]), "r"(b[0]), "r"(b[1]));
}
__device__ __forceinline__ void mma_fp16(float d[4], const uint32_t a[4], const uint32_t b[2]) {
    asm volatile("mma.sync.aligned.m16n8k16.row.col.f32.f16.f16.f32 "
                 "{%0,%1,%2,%3}, {%4,%5,%6,%7}, {%8,%9}, {%0,%1,%2,%3};"
                 : "+f"(d[0]), "+f"(d[1]), "+f"(d[2]), "+f"(d[3])
                 : "r"(a[0]), "r"(a[1]), "r"(a[2]), "r"(a[3]), "r"(b[0]), "r"(b[1]));
}

// bf16x2 pack with round-to-nearest (x -> low half, y -> high half)
__device__ __forceinline__ uint32_t pkbf(float x, float y) {
    uint32_t r;
    asm("cvt.rn.bf16x2.f32 %0, %1, %2;" : "=r"(r) : "f"(y), "f"(x));
    return r;
}
// fp16x2 pack (x -> low half, y -> high half)
__device__ __forceinline__ uint32_t pk16(float x, float y) {
    uint32_t r;
    asm("cvt.rn.f16x2.f32 %0, %1, %2;" : "=r"(r) : "f"(y), "f"(x));
    return r;
}
// truncation-based bf16 hi pair: (x.hi16 | y.hi16<<16) in one PRMT
__device__ __forceinline__ uint32_t hi2(float x, float y) {
    return __byte_perm(__float_as_uint(x), __float_as_uint(y), 0x7632);
}
__device__ __forceinline__ float hif(float x) {
    return __uint_as_float(__float_as_uint(x) & 0xffff0000u);
}
__device__ __forceinline__ float ex2(float x) {
    float y;
    asm("ex2.approx.ftz.f32 %0, %1;" : "=f"(y) : "f"(x));
    return y;
}

__global__ __launch_bounds__(128, 2)
void flash_mma_kernel(const float* __restrict__ Q,
                      const float* __restrict__ K,
                      const float* __restrict__ V,
                      const float* __restrict__ Mk,
                      float* __restrict__ O)
{
    extern __shared__ char smem[];
    const uint32_t sb = smem_u32(smem);
    const int tid  = threadIdx.x;
    const int lane = tid & 31;
    const int wid  = tid >> 5;
    const int bh   = blockIdx.y;
    const int qt   = blockIdx.x;

    const float* Qb = Q + ((size_t)bh * SEQ + (size_t)qt * BM) * HD;
    const float* Kb = K + (size_t)bh * SEQ * HD;
    const float* Vb = V + (size_t)bh * SEQ * HD;

    const int g  = lane >> 3;   // ldmatrix 8x8 tile index
    const int i8 = lane & 7;

    // ---- Load Q tile once (hi = truncated bf16, lo = residual bf16) ----
    for (int j = tid; j < BM * 16; j += 128) {
        int row = j >> 4, c = j & 15;
        float4 v = *(const float4*)(Qb + row * HD + c * 4);
        uint32_t o = sw(row * 128 + c * 8);
        *(uint2*)(smem + SQHI + o) = make_uint2(hi2(v.x, v.y), hi2(v.z, v.w));
        *(uint2*)(smem + SQLO + o) =
            make_uint2(pkbf(v.x - hif(v.x), v.y - hif(v.y)),
                       pkbf(v.z - hif(v.z), v.w - hif(v.w)));
    }

    float Sacc[2][8][4];
    float Oacc[2][8][4];
    float mrun[2][2], lrun[2][2];
    #pragma unroll
    for (int mt = 0; mt < 2; mt++) {
        mrun[mt][0] = -1e30f; mrun[mt][1] = -1e30f;
        lrun[mt][0] = 0.0f;   lrun[mt][1] = 0.0f;
        #pragma unroll
        for (int nt = 0; nt < 8; nt++)
            #pragma unroll
            for (int e = 0; e < 4; e++) Oacc[mt][nt][e] = 0.0f;
    }

    for (int kt = 0; kt < SEQ / BN; kt++) {
        __syncthreads();

        // ---- Load K (hi/lo bf16) + V (fp16) tiles ----
        const float* Kt = Kb + (size_t)kt * BN * HD;
        const float* Vt = Vb + (size_t)kt * BN * HD;
        #pragma unroll
        for (int j = tid; j < BN * 16; j += 128) {
            int row = j >> 4, c = j & 15;
            uint32_t o = sw(row * 128 + c * 8);
            float4 v = *(const float4*)(Kt + row * HD + c * 4);
            *(uint2*)(smem + SKHI + o) = make_uint2(hi2(v.x, v.y), hi2(v.z, v.w));
            *(uint2*)(smem + SKLO + o) =
                make_uint2(pkbf(v.x - hif(v.x), v.y - hif(v.y)),
                           pkbf(v.z - hif(v.z), v.w - hif(v.w)));
            float4 w = *(const float4*)(Vt + row * HD + c * 4);
            *(uint2*)(smem + SV + o) = make_uint2(pk16(w.x, w.y), pk16(w.z, w.w));
        }
        __syncthreads();

        // ---- GEMM1: S = Q K^T (3-pass bf16 hi/lo compensation) ----
        #pragma unroll
        for (int mt = 0; mt < 2; mt++)
            #pragma unroll
            for (int nt = 0; nt < 8; nt++)
                #pragma unroll
                for (int e = 0; e < 4; e++) Sacc[mt][nt][e] = 0.0f;

        #pragma unroll
        for (int kc = 0; kc < 4; kc++) {
            uint32_t aQh[2][4], aQl[2][4];
            #pragma unroll
            for (int mt = 0; mt < 2; mt++) {
                uint32_t arow = wid * 32 + mt * 16 + (g & 1) * 8 + i8;
                uint32_t acol = kc * 16 + (g >> 1) * 8;
                uint32_t o = sw(arow * 128 + acol * 2);
                ldsm4(aQh[mt], sb + SQHI + o);
                ldsm4(aQl[mt], sb + SQLO + o);
            }
            #pragma unroll
            for (int nt2 = 0; nt2 < 4; nt2++) {
                uint32_t brow = nt2 * 16 + (g >> 1) * 8 + i8;
                uint32_t bcol = kc * 16 + (g & 1) * 8;
                uint32_t o = sw(brow * 128 + bcol * 2);
                uint32_t bKh[4], bKl[4];
                ldsm4(bKh, sb + SKHI + o);
                ldsm4(bKl, sb + SKLO + o);
                #pragma unroll
                for (int mt = 0; mt < 2; mt++)
                    #pragma unroll
                    for (int h = 0; h < 2; h++) {
                        mma_bf16(Sacc[mt][nt2 * 2 + h], aQh[mt], bKh + 2 * h);
                        mma_bf16(Sacc[mt][nt2 * 2 + h], aQh[mt], bKl + 2 * h);
                        mma_bf16(Sacc[mt][nt2 * 2 + h], aQl[mt], bKh + 2 * h);
                    }
            }
        }

        // ---- online softmax: add mask, row-max, exponentiate, rescale O ----
        #pragma unroll
        for (int mt = 0; mt < 2; mt++) {
            int grow = qt * BM + wid * 32 + mt * 16 + (lane >> 2);
            float mx0 = -1e30f, mx1 = -1e30f;
            #pragma unroll
            for (int nt = 0; nt < 8; nt++) {
                int gcol = kt * BN + nt * 8 + 2 * (lane & 3);
                float2 m0 = *(const float2*)(Mk + (size_t)grow * SEQ + gcol);
                float2 m1 = *(const float2*)(Mk + (size_t)(grow + 8) * SEQ + gcol);
                Sacc[mt][nt][0] += m0.x;
                Sacc[mt][nt][1] += m0.y;
                Sacc[mt][nt][2] += m1.x;
                Sacc[mt][nt][3] += m1.y;
                mx0 = fmaxf(mx0, fmaxf(Sacc[mt][nt][0], Sacc[mt][nt][1]));
                mx1 = fmaxf(mx1, fmaxf(Sacc[mt][nt][2], Sacc[mt][nt][3]));
            }
            mx0 = fmaxf(mx0, __shfl_xor_sync(0xffffffffu, mx0, 1));
            mx0 = fmaxf(mx0, __shfl_xor_sync(0xffffffffu, mx0, 2));
            mx1 = fmaxf(mx1, __shfl_xor_sync(0xffffffffu, mx1, 1));
            mx1 = fmaxf(mx1, __shfl_xor_sync(0xffffffffu, mx1, 2));

            float mn0 = fmaxf(mrun[mt][0], mx0);
            float mn1 = fmaxf(mrun[mt][1], mx1);
            float corr0 = ex2((mrun[mt][0] - mn0) * LOG2E);
            float corr1 = ex2((mrun[mt][1] - mn1) * LOG2E);
            mrun[mt][0] = mn0;
            mrun[mt][1] = mn1;

            float s0 = 0.0f, s1 = 0.0f;
            #pragma unroll
            for (int nt = 0; nt < 8; nt++) {
                float p0 = ex2((Sacc[mt][nt][0] - mn0) * LOG2E);
                float p1 = ex2((Sacc[mt][nt][1] - mn0) * LOG2E);
                float p2 = ex2((Sacc[mt][nt][2] - mn1) * LOG2E);
                float p3 = ex2((Sacc[mt][nt][3] - mn1) * LOG2E);
                s0 += p0 + p1;
                s1 += p2 + p3;
                Sacc[mt][nt][0] = p0; Sacc[mt][nt][1] = p1;
                Sacc[mt][nt][2] = p2; Sacc[mt][nt][3] = p3;
                Oacc[mt][nt][0] *= corr0; Oacc[mt][nt][1] *= corr0;
                Oacc[mt][nt][2] *= corr1; Oacc[mt][nt][3] *= corr1;
            }
            lrun[mt][0] = lrun[mt][0] * corr0 + s0;
            lrun[mt][1] = lrun[mt][1] * corr1 + s1;
        }

        // ---- GEMM2: O += P V (single-pass fp16, P from registers) ----
        #pragma unroll
        for (int kc = 0; kc < 4; kc++) {
            uint32_t aP[2][4];
            #pragma unroll
            for (int mt = 0; mt < 2; mt++) {
                const float* t0 = Sacc[mt][2 * kc];
                const float* t1 = Sacc[mt][2 * kc + 1];
                aP[mt][0] = pk16(t0[0], t0[1]);
                aP[mt][1] = pk16(t0[2], t0[3]);
                aP[mt][2] = pk16(t1[0], t1[1]);
                aP[mt][3] = pk16(t1[2], t1[3]);
            }
            #pragma unroll
            for (int nt2 = 0; nt2 < 4; nt2++) {
                uint32_t vrow = kc * 16 + (g & 1) * 8 + i8;
                uint32_t vcol = nt2 * 16 + (g >> 1) * 8;
                uint32_t o = sw(vrow * 128 + vcol * 2);
                uint32_t bV[4];
                ldsm4t(bV, sb + SV + o);
                #pragma unroll
                for (int mt = 0; mt < 2; mt++)
                    #pragma unroll
                    for (int h = 0; h < 2; h++)
                        mma_fp16(Oacc[mt][nt2 * 2 + h], aP[mt], bV + 2 * h);
            }
        }
    }

    // ---- epilogue: reduce l over quad, normalize, store ----
    #pragma unroll
    for (int mt = 0; mt < 2; mt++)
        #pragma unroll
        for (int hh = 0; hh < 2; hh++) {
            float s = lrun[mt][hh];
            s += __shfl_xor_sync(0xffffffffu, s, 1);
            s += __shfl_xor_sync(0xffffffffu, s, 2);
            lrun[mt][hh] = s;
        }

    #pragma unroll
    for (int mt = 0; mt < 2; mt++) {
        float inv0 = 1.0f / lrun[mt][0];
        float inv1 = 1.0f / lrun[mt][1];
        int grow = qt * BM + wid * 32 + mt * 16 + (lane >> 2);
        float* o0 = O + ((size_t)bh * SEQ + grow) * HD;
        float* o1 = O + ((size_t)bh * SEQ + grow + 8) * HD;
        #pragma unroll
        for (int nt = 0; nt < 8; nt++) {
            int c = nt * 8 + 2 * (lane & 3);
            *(float2*)(o0 + c) = make_float2(Oacc[mt][nt][0] * inv0, Oacc[mt][nt][1] * inv0);
            *(float2*)(o1 + c) = make_float2(Oacc[mt][nt][2] * inv1, Oacc[mt][nt][3] * inv1);
        }
    }
}

extern "C" void kernel_launch(void* const* d_in, const int* in_sizes, int n_in,
                              void* d_out, int out_size)
{
    const float* Q  = (const float*)d_in[0];
    const float* K  = (const float*)d_in[1];
    const float* V  = (const float*)d_in[2];
    const float* Mk = (const float*)d_in[3];
    float* O = (float*)d_out;

    int bh = in_sizes[0] / (SEQ * HD);   // B*H = 64

    cudaFuncSetAttribute(flash_mma_kernel,
                         cudaFuncAttributeMaxDynamicSharedMemorySize, SMEM_TOTAL);

    dim3 grid(SEQ / BM, bh);
    flash_mma_kernel<<<grid, 128, SMEM_TOTAL>>>(Q, K, V, Mk, O);
}

// round 9
// speedup vs baseline: 4.4334x; 1.2003x over previous
#include <cuda_runtime.h>
#include <cuda_bf16.h>
#include <cstdint>
#include <math.h>

#define SEQ   2048
#define HD    64
#define BM    128
#define BN    64
#define LOG2E 1.4426950408889634f

// smem byte offsets
#define SQHI  0                 // 128 x 128B = 16 KB (Q hi, SW128)
#define SQLO  (16*1024)         // 16 KB (Q lo)
#define SKHI  (32*1024)         //  8 KB (K hi)
#define SKLO  (40*1024)         //  8 KB (K lo)
#define SV    (48*1024)         //  8 KB (V fp16)
#define SMASK (56*1024)         // 128 rows x 288B = 36 KB
#define MROWB 288               // mask row stride in bytes (72 floats)
#define SMEM_TOTAL (56*1024 + 128*MROWB)   // 92 KB

__device__ __forceinline__ uint32_t sw(uint32_t o) { return o ^ ((o >> 3) & 0x70); }

__device__ __forceinline__ uint32_t smem_u32(const void* p) {
    uint32_t a;
    asm("{ .reg .u64 t; cvta.to.shared.u64 t, %1; cvt.u32.u64 %0, t; }" : "=r"(a) : "l"(p));
    return a;
}

__device__ __forceinline__ void cp16(uint32_t dst, const void* src) {
    asm volatile("cp.async.ca.shared.global [%0], [%1], 16;" :: "r"(dst), "l"(src));
}

__device__ __forceinline__ void ldsm4(uint32_t r[4], uint32_t a) {
    asm volatile("ldmatrix.sync.aligned.m8n8.x4.shared.b16 {%0,%1,%2,%3}, [%4];"
                 : "=r"(r[0]), "=r"(r[1]), "=r"(r[2]), "=r"(r[3]) : "r"(a));
}
__device__ __forceinline__ void ldsm4t(uint32_t r[4], uint32_t a) {
    asm volatile("ldmatrix.sync.aligned.m8n8.x4.trans.shared.b16 {%0,%1,%2,%3}, [%4];"
                 : "=r"(r[0]), "=r"(r[1]), "=r"(r[2]), "=r"(r[3]) : "r"(a));
}

__device__ __forceinline__ void mma_bf16(float d[4], const uint32_t a[4], const uint32_t b[2]) {
    asm volatile("mma.sync.aligned.m16n8k16.row.col.f32.bf16.bf16.f32 "
                 "{%0,%1,%2,%3}, {%4,%5,%6,%7}, {%8,%9}, {%0,%1,%2,%3};"
                 : "+f"(d[0]), "+f"(d[1]), "+f"(d[2]), "+f"(d[3])
                 : "r"(a[0]), "r"(a[1]), "r"(a[2]), "r"(a[3]), "r"(b[0]), "r"(b[1]));
}
__device__ __forceinline__ void mma_fp16(float d[4], const uint32_t a[4], const uint32_t b[2]) {
    asm volatile("mma.sync.aligned.m16n8k16.row.col.f32.f16.f16.f32 "
                 "{%0,%1,%2,%3}, {%4,%5,%6,%7}, {%8,%9}, {%0,%1,%2,%3};"
                 : "+f"(d[0]), "+f"(d[1]), "+f"(d[2]), "+f"(d[3])
                 : "r"(a[0]), "r"(a[1]), "r"(a[2]), "r"(a[3]), "r"(b[0]), "r"(b[1]));
}

__device__ __forceinline__ uint32_t pkbf(float x, float y) {
    uint32_t r;
    asm("cvt.rn.bf16x2.f32 %0, %1, %2;" : "=r"(r) : "f"(y), "f"(x));
    return r;
}
__device__ __forceinline__ uint32_t pk16(float x, float y) {
    uint32_t r;
    asm("cvt.rn.f16x2.f32 %0, %1, %2;" : "=r"(r) : "f"(y), "f"(x));
    return r;
}
__device__ __forceinline__ uint32_t hi2(float x, float y) {
    return __byte_perm(__float_as_uint(x), __float_as_uint(y), 0x7632);
}
__device__ __forceinline__ float hif(float x) {
    return __uint_as_float(__float_as_uint(x) & 0xffff0000u);
}
__device__ __forceinline__ float ex2(float x) {
    float y;
    asm("ex2.approx.ftz.f32 %0, %1;" : "=f"(y) : "f"(x));
    return y;
}

__global__ __launch_bounds__(256, 2)
void flash_mma_kernel(const float* __restrict__ Q,
                      const float* __restrict__ K,
                      const float* __restrict__ V,
                      const float* __restrict__ Mk,
                      float* __restrict__ O)
{
    extern __shared__ char smem[];
    const uint32_t sb = smem_u32(smem);
    const int tid  = threadIdx.x;
    const int lane = tid & 31;
    const int wid  = tid >> 5;          // 0..7, each warp = 16 Q rows
    const int bh   = blockIdx.y;
    const int qt   = blockIdx.x;

    const float* Qb = Q + ((size_t)bh * SEQ + (size_t)qt * BM) * HD;
    const float* Kb = K + (size_t)bh * SEQ * HD;
    const float* Vb = V + (size_t)bh * SEQ * HD;
    const float* Mb = Mk + (size_t)(qt * BM) * SEQ;

    const int g  = lane >> 3;
    const int i8 = lane & 7;

    // ---- Load Q tile once (hi trunc-bf16 / lo residual bf16) ----
    for (int j = tid; j < BM * 16; j += 256) {
        int row = j >> 4, c = j & 15;
        float4 v = *(const float4*)(Qb + row * HD + c * 4);
        uint32_t o = sw(row * 128 + c * 8);
        *(uint2*)(smem + SQHI + o) = make_uint2(hi2(v.x, v.y), hi2(v.z, v.w));
        *(uint2*)(smem + SQLO + o) =
            make_uint2(pkbf(v.x - hif(v.x), v.y - hif(v.y)),
                       pkbf(v.z - hif(v.z), v.w - hif(v.w)));
    }

    float Sacc[8][4];
    float Oacc[8][4];
    float mrun0 = -1e30f, mrun1 = -1e30f, lrun0 = 0.0f, lrun1 = 0.0f;
    #pragma unroll
    for (int nt = 0; nt < 8; nt++)
        #pragma unroll
        for (int e = 0; e < 4; e++) Oacc[nt][e] = 0.0f;

    const int r0 = lane >> 2;                        // quad row within strip
    const uint32_t mrow0 = sb + SMASK + (wid * 16 + r0) * MROWB;
    const uint32_t mcol  = (lane & 3) * 8;           // byte offset of float2

    for (int kt = 0; kt < SEQ / BN; kt++) {
        __syncthreads();

        // ---- prefetch mask tile via cp.async (overlaps K/V global loads) ----
        {
            const float* msrc = Mb + kt * BN;
            #pragma unroll
            for (int c = tid; c < BM * 16; c += 256) {
                int row = c >> 4, seg = c & 15;
                cp16(sb + SMASK + row * MROWB + seg * 16,
                     msrc + (size_t)row * SEQ + seg * 4);
            }
        }

        // ---- Load K (hi/lo bf16) + V (fp16) tiles ----
        const float* Kt = Kb + (size_t)kt * BN * HD;
        const float* Vt = Vb + (size_t)kt * BN * HD;
        #pragma unroll
        for (int j = tid; j < BN * 16; j += 256) {
            int row = j >> 4, c = j & 15;
            uint32_t o = sw(row * 128 + c * 8);
            float4 v = *(const float4*)(Kt + row * HD + c * 4);
            *(uint2*)(smem + SKHI + o) = make_uint2(hi2(v.x, v.y), hi2(v.z, v.w));
            *(uint2*)(smem + SKLO + o) =
                make_uint2(pkbf(v.x - hif(v.x), v.y - hif(v.y)),
                           pkbf(v.z - hif(v.z), v.w - hif(v.w)));
            float4 w = *(const float4*)(Vt + row * HD + c * 4);
            *(uint2*)(smem + SV + o) = make_uint2(pk16(w.x, w.y), pk16(w.z, w.w));
        }
        asm volatile("cp.async.wait_all;" ::: "memory");
        __syncthreads();

        // ---- GEMM1: S = Q K^T (3-pass bf16 hi/lo) ----
        #pragma unroll
        for (int nt = 0; nt < 8; nt++)
            #pragma unroll
            for (int e = 0; e < 4; e++) Sacc[nt][e] = 0.0f;

        #pragma unroll
        for (int kc = 0; kc < 4; kc++) {
            uint32_t aQh[4], aQl[4];
            {
                uint32_t arow = wid * 16 + (g & 1) * 8 + i8;
                uint32_t acol = kc * 16 + (g >> 1) * 8;
                uint32_t o = sw(arow * 128 + acol * 2);
                ldsm4(aQh, sb + SQHI + o);
                ldsm4(aQl, sb + SQLO + o);
            }
            #pragma unroll
            for (int nt2 = 0; nt2 < 4; nt2++) {
                uint32_t brow = nt2 * 16 + (g >> 1) * 8 + i8;
                uint32_t bcol = kc * 16 + (g & 1) * 8;
                uint32_t o = sw(brow * 128 + bcol * 2);
                uint32_t bKh[4], bKl[4];
                ldsm4(bKh, sb + SKHI + o);
                ldsm4(bKl, sb + SKLO + o);
                #pragma unroll
                for (int h = 0; h < 2; h++) {
                    mma_bf16(Sacc[nt2 * 2 + h], aQh, bKh + 2 * h);
                    mma_bf16(Sacc[nt2 * 2 + h], aQh, bKl + 2 * h);
                    mma_bf16(Sacc[nt2 * 2 + h], aQl, bKh + 2 * h);
                }
            }
        }

        // ---- online softmax (mask from smem) ----
        {
            float mx0 = -1e30f, mx1 = -1e30f;
            #pragma unroll
            for (int nt = 0; nt < 8; nt++) {
                float2 m0 = *(const float2*)(smem + (mrow0 - sb) + nt * 32 + mcol);
                float2 m1 = *(const float2*)(smem + (mrow0 - sb) + 8 * MROWB + nt * 32 + mcol);
                Sacc[nt][0] += m0.x;
                Sacc[nt][1] += m0.y;
                Sacc[nt][2] += m1.x;
                Sacc[nt][3] += m1.y;
                mx0 = fmaxf(mx0, fmaxf(Sacc[nt][0], Sacc[nt][1]));
                mx1 = fmaxf(mx1, fmaxf(Sacc[nt][2], Sacc[nt][3]));
            }
            mx0 = fmaxf(mx0, __shfl_xor_sync(0xffffffffu, mx0, 1));
            mx0 = fmaxf(mx0, __shfl_xor_sync(0xffffffffu, mx0, 2));
            mx1 = fmaxf(mx1, __shfl_xor_sync(0xffffffffu, mx1, 1));
            mx1 = fmaxf(mx1, __shfl_xor_sync(0xffffffffu, mx1, 2));

            float mn0 = fmaxf(mrun0, mx0);
            float mn1 = fmaxf(mrun1, mx1);
            float corr0 = ex2((mrun0 - mn0) * LOG2E);
            float corr1 = ex2((mrun1 - mn1) * LOG2E);
            mrun0 = mn0; mrun1 = mn1;

            float s0 = 0.0f, s1 = 0.0f;
            #pragma unroll
            for (int nt = 0; nt < 8; nt++) {
                float p0 = ex2((Sacc[nt][0] - mn0) * LOG2E);
                float p1 = ex2((Sacc[nt][1] - mn0) * LOG2E);
                float p2 = ex2((Sacc[nt][2] - mn1) * LOG2E);
                float p3 = ex2((Sacc[nt][3] - mn1) * LOG2E);
                s0 += p0 + p1;
                s1 += p2 + p3;
                Sacc[nt][0] = p0; Sacc[nt][1] = p1;
                Sacc[nt][2] = p2; Sacc[nt][3] = p3;
                Oacc[nt][0] *= corr0; Oacc[nt][1] *= corr0;
                Oacc[nt][2] *= corr1; Oacc[nt][3] *= corr1;
            }
            lrun0 = lrun0 * corr0 + s0;
            lrun1 = lrun1 * corr1 + s1;
        }

        // ---- GEMM2: O += P V (single-pass fp16, P from registers) ----
        #pragma unroll
        for (int kc = 0; kc < 4; kc++) {
            uint32_t aP[4];
            {
                const float* t0 = Sacc[2 * kc];
                const float* t1 = Sacc[2 * kc + 1];
                aP[0] = pk16(t0[0], t0[1]);
                aP[1] = pk16(t0[2], t0[3]);
                aP[2] = pk16(t1[0], t1[1]);
                aP[3] = pk16(t1[2], t1[3]);
            }
            #pragma unroll
            for (int nt2 = 0; nt2 < 4; nt2++) {
                uint32_t vrow = kc * 16 + (g & 1) * 8 + i8;
                uint32_t vcol = nt2 * 16 + (g >> 1) * 8;
                uint32_t o = sw(vrow * 128 + vcol * 2);
                uint32_t bV[4];
                ldsm4t(bV, sb + SV + o);
                #pragma unroll
                for (int h = 0; h < 2; h++)
                    mma_fp16(Oacc[nt2 * 2 + h], aP, bV + 2 * h);
            }
        }
    }

    // ---- epilogue: reduce l over quad, normalize, store ----
    {
        float s0 = lrun0, s1 = lrun1;
        s0 += __shfl_xor_sync(0xffffffffu, s0, 1);
        s0 += __shfl_xor_sync(0xffffffffu, s0, 2);
        s1 += __shfl_xor_sync(0xffffffffu, s1, 1);
        s1 += __shfl_xor_sync(0xffffffffu, s1, 2);
        float inv0 = 1.0f / s0;
        float inv1 = 1.0f / s1;
        int grow = qt * BM + wid * 16 + r0;
        float* o0 = O + ((size_t)bh * SEQ + grow) * HD;
        float* o1 = O + ((size_t)bh * SEQ + grow + 8) * HD;
        #pragma unroll
        for (int nt = 0; nt < 8; nt++) {
            int c = nt * 8 + 2 * (lane & 3);
            *(float2*)(o0 + c) = make_float2(Oacc[nt][0] * inv0, Oacc[nt][1] * inv0);
            *(float2*)(o1 + c) = make_float2(Oacc[nt][2] * inv1, Oacc[nt][3] * inv1);
        }
    }
}

extern "C" void kernel_launch(void* const* d_in, const int* in_sizes, int n_in,
                              void* d_out, int out_size)
{
    const float* Q  = (const float*)d_in[0];
    const float* K  = (const float*)d_in[1];
    const float* V  = (const float*)d_in[2];
    const float* Mk = (const float*)d_in[3];
    float* O = (float*)d_out;

    int bh = in_sizes[0] / (SEQ * HD);   // B*H = 64

    cudaFuncSetAttribute(flash_mma_kernel,
                         cudaFuncAttributeMaxDynamicSharedMemorySize, SMEM_TOTAL);

    dim3 grid(SEQ / BM, bh);
    flash_mma_kernel<<<grid, 256, SMEM_TOTAL>>>(Q, K, V, Mk, O);
}